// round 1
// baseline (speedup 1.0000x reference)
#include <cuda_runtime.h>
#include <cuda_bf16.h>
#include <cstdint>

// Problem constants
#define BATCH   2048
#define NTOK    64
#define DIM     512
#define NH      16
#define HD      32
#define MROWS   (BATCH * NTOK)      // 131072
#define QKVCOLS (3 * DIM)           // 1536
#define SCALE   0.17677669529663687f // 32^-0.5

// Scratch (allocation-free: __device__ globals)
__device__ float g_qkv[(size_t)MROWS * QKVCOLS];   // [B*N, 1536]
__device__ float g_attn[(size_t)MROWS * DIM];      // [B*N, 512]

__device__ __forceinline__ float tf32r(float x) {
    float y;
    asm("cvt.rna.tf32.f32 %0, %1;" : "=f"(y) : "f"(x));
    return y;
}

__device__ __forceinline__ void mma_tf32(float* d, const uint32_t* a, const uint32_t* b) {
    asm volatile(
        "mma.sync.aligned.m16n8k8.row.col.f32.tf32.tf32.f32 "
        "{%0,%1,%2,%3}, {%4,%5,%6,%7}, {%8,%9}, {%0,%1,%2,%3};"
        : "+f"(d[0]), "+f"(d[1]), "+f"(d[2]), "+f"(d[3])
        : "r"(a[0]), "r"(a[1]), "r"(a[2]), "r"(a[3]), "r"(b[0]), "r"(b[1]));
}

// ---------------------------------------------------------------------------
// GEMM: C[M,N] = A[M,K] @ W[N,K]^T + bias[N]   (A,W,C row-major, K contiguous)
// Tiles: 128x128x32, 256 threads = 8 warps (2 x 4), warp tile 64x32.
// ---------------------------------------------------------------------------
#define BM 128
#define BN 128
#define BK 32
#define LDT 36   // BK + 4 pad: conflict-free frag loads, 16B-aligned rows

__global__ void __launch_bounds__(256) gemm_tf32(
    const float* __restrict__ A, const float* __restrict__ W,
    const float* __restrict__ bias, float* __restrict__ C,
    int M, int N, int K)
{
    extern __shared__ float smem[];
    float* As = smem;                        // [2][BM][LDT]
    float* Bs = smem + 2 * BM * LDT;         // [2][BN][LDT]

    const int tid  = threadIdx.x;
    const int lane = tid & 31;
    const int warp = tid >> 5;
    const int wm   = warp >> 2;              // 0..1
    const int wn   = warp & 3;               // 0..3
    const int mb   = blockIdx.y * BM;
    const int nb   = blockIdx.x * BN;

    const int r0 = tid >> 3;                 // base row for gmem f4 loads
    const int c0 = (tid & 7) * 4;            // k offset (floats)

    float4 ra[4], rb[4];
    const int KT = K / BK;

    // prologue: load tile 0
    {
        const float* Ag = A + (size_t)mb * K;
        const float* Wg = W + (size_t)nb * K;
        #pragma unroll
        for (int i = 0; i < 4; i++) {
            ra[i] = *(const float4*)(Ag + (size_t)(r0 + i * 32) * K + c0);
            rb[i] = *(const float4*)(Wg + (size_t)(r0 + i * 32) * K + c0);
        }
        #pragma unroll
        for (int i = 0; i < 4; i++) {
            float4 a = ra[i], b = rb[i];
            a.x = tf32r(a.x); a.y = tf32r(a.y); a.z = tf32r(a.z); a.w = tf32r(a.w);
            b.x = tf32r(b.x); b.y = tf32r(b.y); b.z = tf32r(b.z); b.w = tf32r(b.w);
            *(float4*)(As + (size_t)(r0 + i * 32) * LDT + c0) = a;
            *(float4*)(Bs + (size_t)(r0 + i * 32) * LDT + c0) = b;
        }
    }

    float acc[4][4][4] = {};

    for (int kt = 0; kt < KT; ++kt) {
        __syncthreads();
        if (kt + 1 < KT) {
            const float* Ag = A + (size_t)mb * K + (kt + 1) * BK;
            const float* Wg = W + (size_t)nb * K + (kt + 1) * BK;
            #pragma unroll
            for (int i = 0; i < 4; i++) {
                ra[i] = *(const float4*)(Ag + (size_t)(r0 + i * 32) * K + c0);
                rb[i] = *(const float4*)(Wg + (size_t)(r0 + i * 32) * K + c0);
            }
        }
        const int buf = kt & 1;
        const float* Ab = As + buf * BM * LDT + (wm * 64) * LDT;
        const float* Bb = Bs + buf * BN * LDT + (wn * 32) * LDT;

        #pragma unroll
        for (int ks = 0; ks < 4; ks++) {
            const int k8 = ks * 8;
            uint32_t afr[4][4], bfr[4][2];
            #pragma unroll
            for (int mi = 0; mi < 4; mi++) {
                const float* p = Ab + (mi * 16 + (lane >> 2)) * LDT + k8 + (lane & 3);
                afr[mi][0] = __float_as_uint(p[0]);
                afr[mi][1] = __float_as_uint(p[8 * LDT]);
                afr[mi][2] = __float_as_uint(p[4]);
                afr[mi][3] = __float_as_uint(p[8 * LDT + 4]);
            }
            #pragma unroll
            for (int ni = 0; ni < 4; ni++) {
                const float* p = Bb + (ni * 8 + (lane >> 2)) * LDT + k8 + (lane & 3);
                bfr[ni][0] = __float_as_uint(p[0]);
                bfr[ni][1] = __float_as_uint(p[4]);
            }
            #pragma unroll
            for (int mi = 0; mi < 4; mi++)
                #pragma unroll
                for (int ni = 0; ni < 4; ni++)
                    mma_tf32(acc[mi][ni], afr[mi], bfr[ni]);
        }

        if (kt + 1 < KT) {
            const int nbuf = (kt + 1) & 1;
            float* Ad = As + nbuf * BM * LDT;
            float* Bd = Bs + nbuf * BN * LDT;
            #pragma unroll
            for (int i = 0; i < 4; i++) {
                float4 a = ra[i], b = rb[i];
                a.x = tf32r(a.x); a.y = tf32r(a.y); a.z = tf32r(a.z); a.w = tf32r(a.w);
                b.x = tf32r(b.x); b.y = tf32r(b.y); b.z = tf32r(b.z); b.w = tf32r(b.w);
                *(float4*)(Ad + (size_t)(r0 + i * 32) * LDT + c0) = a;
                *(float4*)(Bd + (size_t)(r0 + i * 32) * LDT + c0) = b;
            }
        }
    }

    // epilogue: +bias, fp32 stores
    #pragma unroll
    for (int mi = 0; mi < 4; mi++) {
        const int row = mb + wm * 64 + mi * 16 + (lane >> 2);
        #pragma unroll
        for (int ni = 0; ni < 4; ni++) {
            const int col = nb + wn * 32 + ni * 8 + (lane & 3) * 2;
            const float b0 = bias[col], b1 = bias[col + 1];
            float* Cp = C + (size_t)row * N + col;
            float2 v0 = make_float2(acc[mi][ni][0] + b0, acc[mi][ni][1] + b1);
            float2 v1 = make_float2(acc[mi][ni][2] + b0, acc[mi][ni][3] + b1);
            *(float2*)Cp = v0;
            *(float2*)(Cp + (size_t)8 * N) = v1;
        }
    }
}

// ---------------------------------------------------------------------------
// Attention: one (b, h) per block. 128 threads = 4 warps.
// S = (Q*scale) K^T + bias(rel-pos), softmax rows, O = P V.
// ---------------------------------------------------------------------------
__global__ void __launch_bounds__(128) attn_kernel(
    const float* __restrict__ qkv, const float* __restrict__ btab,
    float* __restrict__ out)
{
    __shared__ float Qs[64][36];
    __shared__ float Ks[64][36];
    __shared__ float S[64][68];
    __shared__ float Vt[32][68];

    const int bh = blockIdx.x;
    const int b = bh >> 4;
    const int h = bh & 15;
    const int tid = threadIdx.x;
    const int lane = tid & 31;
    const int warp = tid >> 5;

    const float* base = qkv + (size_t)b * NTOK * QKVCOLS + h * HD;

    // Load Q (pre-scaled), K — 512 float4 each; V transposed
    #pragma unroll
    for (int i = 0; i < 4; i++) {
        const int id = tid + i * 128;            // 0..511
        const int n = id >> 3;
        const int c4 = (id & 7) * 4;
        float4 q = *(const float4*)(base + (size_t)n * QKVCOLS + c4);
        q.x = tf32r(q.x * SCALE); q.y = tf32r(q.y * SCALE);
        q.z = tf32r(q.z * SCALE); q.w = tf32r(q.w * SCALE);
        *(float4*)(&Qs[n][c4]) = q;
        float4 k = *(const float4*)(base + (size_t)n * QKVCOLS + DIM + c4);
        k.x = tf32r(k.x); k.y = tf32r(k.y); k.z = tf32r(k.z); k.w = tf32r(k.w);
        *(float4*)(&Ks[n][c4]) = k;
    }
    for (int i = tid; i < NTOK * HD; i += 128) {
        const int m = i >> 5, d = i & 31;
        Vt[d][m] = tf32r(base[(size_t)m * QKVCOLS + 2 * DIM + d]);
    }
    __syncthreads();

    // --- S = Qs @ Ks^T : each warp does rows [warp*16, warp*16+16) ---
    float sacc[8][4] = {};
    #pragma unroll
    for (int ks = 0; ks < 4; ks++) {
        const int k8 = ks * 8;
        uint32_t af[4];
        const float* p = &Qs[warp * 16 + (lane >> 2)][k8 + (lane & 3)];
        af[0] = __float_as_uint(p[0]);
        af[1] = __float_as_uint(p[8 * 36]);
        af[2] = __float_as_uint(p[4]);
        af[3] = __float_as_uint(p[8 * 36 + 4]);
        #pragma unroll
        for (int ni = 0; ni < 8; ni++) {
            uint32_t bf[2];
            const float* q = &Ks[ni * 8 + (lane >> 2)][k8 + (lane & 3)];
            bf[0] = __float_as_uint(q[0]);
            bf[1] = __float_as_uint(q[4]);
            mma_tf32(sacc[ni], af, bf);
        }
    }
    // epilogue: + relative-position bias, into S
    {
        const int rA = warp * 16 + (lane >> 2);
        #pragma unroll
        for (int ni = 0; ni < 8; ni++) {
            #pragma unroll
            for (int e = 0; e < 4; e++) {
                const int row = rA + ((e >= 2) ? 8 : 0);
                const int col = ni * 8 + (lane & 3) * 2 + (e & 1);
                const int yi = row >> 3, xi = row & 7;
                const int yj = col >> 3, xj = col & 7;
                const int idx = (yi - yj + 7) * 15 + (xi - xj + 7);
                S[row][col] = sacc[ni][e] + btab[idx * NH + h];
            }
        }
    }
    __syncthreads();

    // --- softmax: 2 threads per row ---
    {
        const int row = tid >> 1;
        const int half = (tid & 1) * 32;
        float mx = -1e30f;
        #pragma unroll
        for (int j = 0; j < 32; j++) mx = fmaxf(mx, S[row][half + j]);
        mx = fmaxf(mx, __shfl_xor_sync(0xffffffffu, mx, 1));
        float ev[32];
        float sum = 0.f;
        #pragma unroll
        for (int j = 0; j < 32; j++) { ev[j] = __expf(S[row][half + j] - mx); sum += ev[j]; }
        sum += __shfl_xor_sync(0xffffffffu, sum, 1);
        const float inv = 1.f / sum;
        #pragma unroll
        for (int j = 0; j < 32; j++) S[row][half + j] = tf32r(ev[j] * inv);
    }
    __syncthreads();

    // --- O = P @ V : P=S (A op, K=64), Vt (B op [d][m]) ---
    float oacc[4][4] = {};
    #pragma unroll
    for (int ks = 0; ks < 8; ks++) {
        const int k8 = ks * 8;
        uint32_t af[4];
        const float* p = &S[warp * 16 + (lane >> 2)][k8 + (lane & 3)];
        af[0] = __float_as_uint(p[0]);
        af[1] = __float_as_uint(p[8 * 68]);
        af[2] = __float_as_uint(p[4]);
        af[3] = __float_as_uint(p[8 * 68 + 4]);
        #pragma unroll
        for (int ni = 0; ni < 4; ni++) {
            uint32_t bf[2];
            const float* q = &Vt[ni * 8 + (lane >> 2)][k8 + (lane & 3)];
            bf[0] = __float_as_uint(q[0]);
            bf[1] = __float_as_uint(q[4]);
            mma_tf32(oacc[ni], af, bf);
        }
    }
    // write out[b][row][h*32 + col]
    {
        float* ob = out + (size_t)b * NTOK * DIM + h * HD;
        const int rA = warp * 16 + (lane >> 2);
        #pragma unroll
        for (int ni = 0; ni < 4; ni++) {
            const int col = ni * 8 + (lane & 3) * 2;
            *(float2*)(ob + (size_t)rA * DIM + col) =
                make_float2(oacc[ni][0], oacc[ni][1]);
            *(float2*)(ob + (size_t)(rA + 8) * DIM + col) =
                make_float2(oacc[ni][2], oacc[ni][3]);
        }
    }
}

// ---------------------------------------------------------------------------
extern "C" void kernel_launch(void* const* d_in, const int* in_sizes, int n_in,
                              void* d_out, int out_size)
{
    const float* x     = (const float*)d_in[0];
    const float* Wqkv  = (const float*)d_in[1];
    const float* bqkv  = (const float*)d_in[2];
    const float* Wproj = (const float*)d_in[3];
    const float* bproj = (const float*)d_in[4];
    const float* btab  = (const float*)d_in[5];
    float* out = (float*)d_out;

    float *qkvbuf, *attnbuf;
    cudaGetSymbolAddress((void**)&qkvbuf, g_qkv);
    cudaGetSymbolAddress((void**)&attnbuf, g_attn);

    const int smem = 2 * (BM + BN) * LDT * (int)sizeof(float);   // 73728 B
    cudaFuncSetAttribute(gemm_tf32, cudaFuncAttributeMaxDynamicSharedMemorySize, smem);

    // 1) QKV projection: [131072, 512] @ [1536, 512]^T + b_qkv
    gemm_tf32<<<dim3(QKVCOLS / BN, MROWS / BM), 256, smem>>>(
        x, Wqkv, bqkv, qkvbuf, MROWS, QKVCOLS, DIM);

    // 2) Windowed attention per (b, h)
    attn_kernel<<<BATCH * NH, 128>>>(qkvbuf, btab, attnbuf);

    // 3) Output projection: [131072, 512] @ [512, 512]^T + b_proj
    gemm_tf32<<<dim3(DIM / BN, MROWS / BM), 256, smem>>>(
        attnbuf, Wproj, bproj, out, MROWS, DIM, DIM);
}

// round 3
// speedup vs baseline: 1.1937x; 1.1937x over previous
#include <cuda_runtime.h>
#include <cstdint>

// Problem constants
#define BATCH   2048
#define NTOK    64
#define DIM     512
#define NH      16
#define HD      32
#define MROWS   (BATCH * NTOK)      // 131072
#define QKVCOLS (3 * DIM)           // 1536
#define SCALE   0.17677669529663687f // 32^-0.5

// Scratch (allocation-free: __device__ globals)
__device__ float g_qkv[(size_t)MROWS * QKVCOLS];   // [B*N, 1536]
__device__ float g_attn[(size_t)MROWS * DIM];      // [B*N, 512] (tf32-rounded)
__device__ float g_xr[(size_t)MROWS * DIM];        // tf32-rounded x
__device__ float g_wqkv[(size_t)QKVCOLS * DIM];    // tf32-rounded W_qkv
__device__ float g_wproj[(size_t)DIM * DIM];       // tf32-rounded W_proj

__device__ __forceinline__ float tf32r(float x) {
    float y;
    asm("cvt.rna.tf32.f32 %0, %1;" : "=f"(y) : "f"(x));
    return y;
}

__device__ __forceinline__ uint32_t smem_u32(const void* p) {
    uint32_t a;
    asm("{ .reg .u64 t; cvta.to.shared.u64 t, %1; cvt.u32.u64 %0, t; }" : "=r"(a) : "l"(p));
    return a;
}

__device__ __forceinline__ void cp16(uint32_t s, const void* g) {
    asm volatile("cp.async.cg.shared.global [%0], [%1], 16;" :: "r"(s), "l"(g));
}

__device__ __forceinline__ void mma_tf32(float* d, const uint32_t* a, const uint32_t* b) {
    asm volatile(
        "mma.sync.aligned.m16n8k8.row.col.f32.tf32.tf32.f32 "
        "{%0,%1,%2,%3}, {%4,%5,%6,%7}, {%8,%9}, {%0,%1,%2,%3};"
        : "+f"(d[0]), "+f"(d[1]), "+f"(d[2]), "+f"(d[3])
        : "r"(a[0]), "r"(a[1]), "r"(a[2]), "r"(a[3]), "r"(b[0]), "r"(b[1]));
}

// ---------------------------------------------------------------------------
// Pre-round pass: out[i] = tf32_rna(in[i])  (float4 grid-stride)
// ---------------------------------------------------------------------------
__global__ void __launch_bounds__(256) round4(const float4* __restrict__ in,
                                              float4* __restrict__ out, int n4) {
    int i = blockIdx.x * blockDim.x + threadIdx.x;
    if (i < n4) {
        float4 v = in[i];
        v.x = tf32r(v.x); v.y = tf32r(v.y); v.z = tf32r(v.z); v.w = tf32r(v.w);
        out[i] = v;
    }
}

// ---------------------------------------------------------------------------
// GEMM: C[M,N] = A[M,K] @ W[N,K]^T + bias[N]   (A,W pre-rounded to tf32)
// 128x128x32 tiles, 256 threads (8 warps, 2x4), warp tile 64x32.
// cp.async 3-stage pipeline, padded rows (LDT=36 floats / 144B).
// ---------------------------------------------------------------------------
#define BM 128
#define BN 128
#define BK 32
#define LDT 36
#define ROWB 144                         // bytes per smem row
#define STG_A (128 * ROWB)               // 18432 B
#define STG (2 * STG_A)                  // 36864 B per stage (A then B)
#define STAGES 3
#define GSMEM (STAGES * STG)             // 110592 B

__global__ void __launch_bounds__(256, 2) gemm_hmma(
    const float* __restrict__ A, const float* __restrict__ W,
    const float* __restrict__ bias, float* __restrict__ C,
    int N, int K)
{
    extern __shared__ float smem[];
    const uint32_t sb = smem_u32(smem);
    const int tid  = threadIdx.x;
    const int lane = tid & 31;
    const int warp = tid >> 5;
    const int wm   = warp >> 2;              // 0..1
    const int wn   = warp & 3;               // 0..3
    const int mb   = blockIdx.y * BM;
    const int nb   = blockIdx.x * BN;

    // cp.async mapping: 8 rows x 8 chunks(16B) per 64-thread group; p adds 32 rows
    const int jr = tid >> 3;                 // row 0..31 (+32p)
    const int cb = tid & 7;                  // 16B chunk within row
    const float* Ag = A + (size_t)(mb + jr) * K + cb * 4;
    const float* Wg = W + (size_t)(nb + jr) * K + cb * 4;
    const uint32_t soff = (uint32_t)(jr * ROWB + cb * 16);

    // prologue: stages 0..2
    #pragma unroll
    for (int s = 0; s < STAGES; s++) {
        const uint32_t b = sb + s * STG;
        #pragma unroll
        for (int p = 0; p < 4; p++)
            cp16(b + soff + p * 32 * ROWB, Ag + s * BK + (size_t)p * 32 * K);
        #pragma unroll
        for (int p = 0; p < 4; p++)
            cp16(b + STG_A + soff + p * 32 * ROWB, Wg + s * BK + (size_t)p * 32 * K);
        asm volatile("cp.async.commit_group;" ::: "memory");
    }

    float acc[4][4][4] = {};
    const int KT = K / BK;

    for (int kt = 0; kt < KT; kt++) {
        asm volatile("cp.async.wait_group %0;" :: "n"(STAGES - 1) : "memory");
        __syncthreads();
        const int buf = kt % STAGES;
        const float* Ab = smem + buf * (STG / 4) + (wm * 64) * LDT;
        const float* Bb = smem + buf * (STG / 4) + (STG_A / 4) + (wn * 32) * LDT;

        #pragma unroll
        for (int ks = 0; ks < 4; ks++) {
            const int k8 = ks * 8;
            uint32_t afr[4][4], bfr[4][2];
            #pragma unroll
            for (int mi = 0; mi < 4; mi++) {
                const float* p = Ab + (mi * 16 + (lane >> 2)) * LDT + k8 + (lane & 3);
                afr[mi][0] = __float_as_uint(p[0]);
                afr[mi][1] = __float_as_uint(p[8 * LDT]);
                afr[mi][2] = __float_as_uint(p[4]);
                afr[mi][3] = __float_as_uint(p[8 * LDT + 4]);
            }
            #pragma unroll
            for (int ni = 0; ni < 4; ni++) {
                const float* p = Bb + (ni * 8 + (lane >> 2)) * LDT + k8 + (lane & 3);
                bfr[ni][0] = __float_as_uint(p[0]);
                bfr[ni][1] = __float_as_uint(p[4]);
            }
            #pragma unroll
            for (int mi = 0; mi < 4; mi++)
                #pragma unroll
                for (int ni = 0; ni < 4; ni++)
                    mma_tf32(acc[mi][ni], afr[mi], bfr[ni]);
        }
        __syncthreads();

        const int nk = kt + STAGES;
        if (nk < KT) {
            const uint32_t b = sb + buf * STG;
            #pragma unroll
            for (int p = 0; p < 4; p++)
                cp16(b + soff + p * 32 * ROWB, Ag + nk * BK + (size_t)p * 32 * K);
            #pragma unroll
            for (int p = 0; p < 4; p++)
                cp16(b + STG_A + soff + p * 32 * ROWB, Wg + nk * BK + (size_t)p * 32 * K);
            asm volatile("cp.async.commit_group;" ::: "memory");
        }
    }

    // epilogue: +bias, fp32 stores
    #pragma unroll
    for (int mi = 0; mi < 4; mi++) {
        const int row = mb + wm * 64 + mi * 16 + (lane >> 2);
        #pragma unroll
        for (int ni = 0; ni < 4; ni++) {
            const int col = nb + wn * 32 + ni * 8 + (lane & 3) * 2;
            const float b0 = __ldg(bias + col), b1 = __ldg(bias + col + 1);
            float* Cp = C + (size_t)row * N + col;
            *(float2*)Cp = make_float2(acc[mi][ni][0] + b0, acc[mi][ni][1] + b1);
            *(float2*)(Cp + (size_t)8 * N) =
                make_float2(acc[mi][ni][2] + b0, acc[mi][ni][3] + b1);
        }
    }
}

// ---------------------------------------------------------------------------
// Attention: one (b, h) per block, 128 threads, mma.sync.
// Output stored tf32-rounded (feeds proj GEMM directly via cp.async).
// ---------------------------------------------------------------------------
__global__ void __launch_bounds__(128) attn_kernel(
    const float* __restrict__ qkv, const float* __restrict__ btab,
    float* __restrict__ out)
{
    __shared__ float Qs[64][36];
    __shared__ float Ks[64][36];
    __shared__ float S[64][68];
    __shared__ float Vt[32][68];

    const int bh = blockIdx.x;
    const int b = bh >> 4;
    const int h = bh & 15;
    const int tid = threadIdx.x;
    const int lane = tid & 31;
    const int warp = tid >> 5;

    const float* base = qkv + (size_t)b * NTOK * QKVCOLS + h * HD;

    #pragma unroll
    for (int i = 0; i < 4; i++) {
        const int id = tid + i * 128;
        const int n = id >> 3;
        const int c4 = (id & 7) * 4;
        float4 q = *(const float4*)(base + (size_t)n * QKVCOLS + c4);
        q.x = tf32r(q.x * SCALE); q.y = tf32r(q.y * SCALE);
        q.z = tf32r(q.z * SCALE); q.w = tf32r(q.w * SCALE);
        *(float4*)(&Qs[n][c4]) = q;
        float4 k = *(const float4*)(base + (size_t)n * QKVCOLS + DIM + c4);
        k.x = tf32r(k.x); k.y = tf32r(k.y); k.z = tf32r(k.z); k.w = tf32r(k.w);
        *(float4*)(&Ks[n][c4]) = k;
    }
    for (int i = tid; i < NTOK * HD; i += 128) {
        const int m = i >> 5, d = i & 31;
        Vt[d][m] = tf32r(base[(size_t)m * QKVCOLS + 2 * DIM + d]);
    }
    __syncthreads();

    float sacc[8][4] = {};
    #pragma unroll
    for (int ks = 0; ks < 4; ks++) {
        const int k8 = ks * 8;
        uint32_t af[4];
        const float* p = &Qs[warp * 16 + (lane >> 2)][k8 + (lane & 3)];
        af[0] = __float_as_uint(p[0]);
        af[1] = __float_as_uint(p[8 * 36]);
        af[2] = __float_as_uint(p[4]);
        af[3] = __float_as_uint(p[8 * 36 + 4]);
        #pragma unroll
        for (int ni = 0; ni < 8; ni++) {
            uint32_t bf[2];
            const float* q = &Ks[ni * 8 + (lane >> 2)][k8 + (lane & 3)];
            bf[0] = __float_as_uint(q[0]);
            bf[1] = __float_as_uint(q[4]);
            mma_tf32(sacc[ni], af, bf);
        }
    }
    {
        const int rA = warp * 16 + (lane >> 2);
        #pragma unroll
        for (int ni = 0; ni < 8; ni++) {
            #pragma unroll
            for (int e = 0; e < 4; e++) {
                const int row = rA + ((e >= 2) ? 8 : 0);
                const int col = ni * 8 + (lane & 3) * 2 + (e & 1);
                const int yi = row >> 3, xi = row & 7;
                const int yj = col >> 3, xj = col & 7;
                const int idx = (yi - yj + 7) * 15 + (xi - xj + 7);
                S[row][col] = sacc[ni][e] + btab[idx * NH + h];
            }
        }
    }
    __syncthreads();

    {
        const int row = tid >> 1;
        const int half = (tid & 1) * 32;
        float mx = -1e30f;
        #pragma unroll
        for (int j = 0; j < 32; j++) mx = fmaxf(mx, S[row][half + j]);
        mx = fmaxf(mx, __shfl_xor_sync(0xffffffffu, mx, 1));
        float ev[32];
        float sum = 0.f;
        #pragma unroll
        for (int j = 0; j < 32; j++) { ev[j] = __expf(S[row][half + j] - mx); sum += ev[j]; }
        sum += __shfl_xor_sync(0xffffffffu, sum, 1);
        const float inv = 1.f / sum;
        #pragma unroll
        for (int j = 0; j < 32; j++) S[row][half + j] = tf32r(ev[j] * inv);
    }
    __syncthreads();

    float oacc[4][4] = {};
    #pragma unroll
    for (int ks = 0; ks < 8; ks++) {
        const int k8 = ks * 8;
        uint32_t af[4];
        const float* p = &S[warp * 16 + (lane >> 2)][k8 + (lane & 3)];
        af[0] = __float_as_uint(p[0]);
        af[1] = __float_as_uint(p[8 * 68]);
        af[2] = __float_as_uint(p[4]);
        af[3] = __float_as_uint(p[8 * 68 + 4]);
        #pragma unroll
        for (int ni = 0; ni < 4; ni++) {
            uint32_t bf[2];
            const float* q = &Vt[ni * 8 + (lane >> 2)][k8 + (lane & 3)];
            bf[0] = __float_as_uint(q[0]);
            bf[1] = __float_as_uint(q[4]);
            mma_tf32(oacc[ni], af, bf);
        }
    }
    {
        float* ob = out + (size_t)b * NTOK * DIM + h * HD;
        const int rA = warp * 16 + (lane >> 2);
        #pragma unroll
        for (int ni = 0; ni < 4; ni++) {
            const int col = ni * 8 + (lane & 3) * 2;
            *(float2*)(ob + (size_t)rA * DIM + col) =
                make_float2(tf32r(oacc[ni][0]), tf32r(oacc[ni][1]));
            *(float2*)(ob + (size_t)(rA + 8) * DIM + col) =
                make_float2(tf32r(oacc[ni][2]), tf32r(oacc[ni][3]));
        }
    }
}

// ---------------------------------------------------------------------------
extern "C" void kernel_launch(void* const* d_in, const int* in_sizes, int n_in,
                              void* d_out, int out_size)
{
    const float* x     = (const float*)d_in[0];
    const float* Wqkv  = (const float*)d_in[1];
    const float* bqkv  = (const float*)d_in[2];
    const float* Wproj = (const float*)d_in[3];
    const float* bproj = (const float*)d_in[4];
    const float* btab  = (const float*)d_in[5];
    float* out = (float*)d_out;

    float *qkvbuf, *attnbuf, *xr, *wqkvr, *wprojr;
    cudaGetSymbolAddress((void**)&qkvbuf, g_qkv);
    cudaGetSymbolAddress((void**)&attnbuf, g_attn);
    cudaGetSymbolAddress((void**)&xr, g_xr);
    cudaGetSymbolAddress((void**)&wqkvr, g_wqkv);
    cudaGetSymbolAddress((void**)&wprojr, g_wproj);

    cudaFuncSetAttribute(gemm_hmma, cudaFuncAttributeMaxDynamicSharedMemorySize, GSMEM);

    // 0) tf32-round inputs once
    {
        int n4 = MROWS * DIM / 4;
        round4<<<(n4 + 255) / 256, 256>>>((const float4*)x, (float4*)xr, n4);
        n4 = QKVCOLS * DIM / 4;
        round4<<<(n4 + 255) / 256, 256>>>((const float4*)Wqkv, (float4*)wqkvr, n4);
        n4 = DIM * DIM / 4;
        round4<<<(n4 + 255) / 256, 256>>>((const float4*)Wproj, (float4*)wprojr, n4);
    }

    // 1) QKV projection: [131072, 512] @ [1536, 512]^T + b_qkv
    gemm_hmma<<<dim3(QKVCOLS / BN, MROWS / BM), 256, GSMEM>>>(
        xr, wqkvr, bqkv, qkvbuf, QKVCOLS, DIM);

    // 2) Windowed attention per (b, h)
    attn_kernel<<<BATCH * NH, 128>>>(qkvbuf, btab, attnbuf);

    // 3) Output projection: [131072, 512] @ [512, 512]^T + b_proj
    gemm_hmma<<<dim3(DIM / BN, MROWS / BM), 256, GSMEM>>>(
        attnbuf, wprojr, bproj, out, DIM, DIM);
}